// round 7
// baseline (speedup 1.0000x reference)
#include <cuda_runtime.h>
#include <cuda_bf16.h>
#include <cstdint>
#include <cstddef>

#define NN 4096
#define FF 128
#define SPLITK 4
#define BK 32
#define KTILES ((NN / SPLITK) / BK)   // 32
#define STAGES 4
#define STAGE_BYTES 32768
#define AH_OFF 0
#define AL_OFF 8192
#define BH_OFF 16384
#define BL_OFF 24576

// ---------------- scratch ----------------
__device__ float g_srow[NN];
__device__ float g_scol[NN];
__device__ float2 g_ecs[NN];
__device__ float g_er1u[NN];
__device__ float g_er2u[NN];
__device__ float2 g_ers[NN];
__device__ int   g_perm[NN];
__device__ int   g_irank[NN];
__device__ int   g_mj[NN];
__device__ float g_part[(size_t)SPLITK * NN * FF];
__device__ __nv_bfloat16 g_Bh[NN * FF];
__device__ __nv_bfloat16 g_Bl[NN * FF];
__device__ __nv_bfloat16 g_AttH[(size_t)NN * NN];
__device__ __nv_bfloat16 g_AttL[(size_t)NN * NN];
__device__ __nv_bfloat16 g_AH[(size_t)NN * NN];
__device__ __nv_bfloat16 g_AL[(size_t)NN * NN];

// ---------------- helpers ----------------
__device__ __forceinline__ uint32_t smem_u32(const void* p) {
    uint32_t a;
    asm("{ .reg .u64 t; cvta.to.shared.u64 t, %1; cvt.u32.u64 %0, t; }" : "=r"(a) : "l"(p));
    return a;
}
__device__ __forceinline__ void ldsm4(uint32_t* r, uint32_t a) {
    asm volatile("ldmatrix.sync.aligned.m8n8.x4.shared.b16 {%0,%1,%2,%3}, [%4];"
        : "=r"(r[0]), "=r"(r[1]), "=r"(r[2]), "=r"(r[3]) : "r"(a));
}
__device__ __forceinline__ void ldsm4t(uint32_t* r, uint32_t a) {
    asm volatile("ldmatrix.sync.aligned.m8n8.x4.trans.shared.b16 {%0,%1,%2,%3}, [%4];"
        : "=r"(r[0]), "=r"(r[1]), "=r"(r[2]), "=r"(r[3]) : "r"(a));
}
__device__ __forceinline__ void mma16816(float* d, const uint32_t* a, const uint32_t* b) {
    asm volatile(
        "mma.sync.aligned.m16n8k16.row.col.f32.bf16.bf16.f32 "
        "{%0,%1,%2,%3}, {%4,%5,%6,%7}, {%8,%9}, {%0,%1,%2,%3};"
        : "+f"(d[0]), "+f"(d[1]), "+f"(d[2]), "+f"(d[3])
        : "r"(a[0]), "r"(a[1]), "r"(a[2]), "r"(a[3]), "r"(b[0]), "r"(b[1]));
}
__device__ __forceinline__ void split_bf16(float f, uint16_t& h, uint16_t& l) {
    __nv_bfloat16 hb = __float2bfloat16_rn(f);
    float r = f - __bfloat162float(hb);
    __nv_bfloat16 lb = __float2bfloat16_rn(r);
    h = *(uint16_t*)&hb;
    l = *(uint16_t*)&lb;
}
#define CP16(dst, src) \
    asm volatile("cp.async.cg.shared.global [%0], [%1], 16;" :: "r"(dst), "l"(src))
#define CP_COMMIT() asm volatile("cp.async.commit_group;" ::: "memory")
#define CP_WAIT2() asm volatile("cp.async.wait_group 2;" ::: "memory")

// ---------------- K1: XW = X @ W, emit bf16(XW) + sums + exp factors ----------------
__global__ __launch_bounds__(128) void k_xw(const float* __restrict__ X,
                                            const float* __restrict__ W,
                                            const float* __restrict__ av) {
    __shared__ float xr[16][FF];
    int j = threadIdx.x;
    int i0 = blockIdx.x * 16;
#pragma unroll
    for (int r = 0; r < 16; r++) xr[r][j] = X[(size_t)(i0 + r) * FF + j];
    __syncthreads();
    float acc[16];
#pragma unroll
    for (int r = 0; r < 16; r++) acc[r] = 0.f;
    for (int k = 0; k < FF; k++) {
        float w = W[k * FF + j];
#pragma unroll
        for (int r = 0; r < 16; r++) acc[r] += xr[r][k] * w;
    }
#pragma unroll
    for (int r = 0; r < 16; r++) {
        size_t idx = (size_t)(i0 + r) * FF + j;
        uint16_t h, l;
        split_bf16(acc[r], h, l);
        g_Bh[idx] = *(__nv_bfloat16*)&h;
        g_Bl[idx] = *(__nv_bfloat16*)&l;
    }
    float ac = av[j], ar = av[FF + j];
    int lane = j & 31, w4 = j >> 5;
    __syncthreads();
#pragma unroll
    for (int r = 0; r < 16; r++) xr[r][j] = acc[r] * ac;
    __syncthreads();
#pragma unroll
    for (int rr = 0; rr < 4; rr++) {
        int r = w4 * 4 + rr;
        float v = xr[r][lane] + xr[r][lane + 32] + xr[r][lane + 64] + xr[r][lane + 96];
#pragma unroll
        for (int off = 16; off; off >>= 1) v += __shfl_down_sync(0xffffffffu, v, off);
        if (lane == 0) {
            g_scol[i0 + r] = v;
            g_ecs[i0 + r] = make_float2(expf(0.01f * v), expf(v));
        }
    }
    __syncthreads();
#pragma unroll
    for (int r = 0; r < 16; r++) xr[r][j] = acc[r] * ar;
    __syncthreads();
#pragma unroll
    for (int rr = 0; rr < 4; rr++) {
        int r = w4 * 4 + rr;
        float v = xr[r][lane] + xr[r][lane + 32] + xr[r][lane + 64] + xr[r][lane + 96];
#pragma unroll
        for (int off = 16; off; off >>= 1) v += __shfl_down_sync(0xffffffffu, v, off);
        if (lane == 0) {
            g_srow[i0 + r] = v;
            g_er1u[i0 + r] = expf(0.01f * v);
            g_er2u[i0 + r] = expf(v);
        }
    }
}

// ---------------- K2: bitonic sort + sorted factors + irank + m_j ----------------
__global__ __launch_bounds__(1024) void k_sort() {
    __shared__ float kk[NN];
    __shared__ int   id[NN];
    int tid = threadIdx.x;
    for (int r = tid; r < NN; r += 1024) { kk[r] = g_srow[r]; id[r] = r; }
    __syncthreads();
    for (int sz = 2; sz <= NN; sz <<= 1) {
        for (int st = sz >> 1; st > 0; st >>= 1) {
#pragma unroll
            for (int q = 0; q < 4; q++) {
                int i = tid + q * 1024;
                int j = i ^ st;
                if (j > i) {
                    bool up = ((i & sz) == 0);
                    float ki = kk[i], kj = kk[j];
                    bool swap = up ? (ki > kj) : (ki < kj);
                    if (swap) {
                        kk[i] = kj; kk[j] = ki;
                        int ti = id[i]; id[i] = id[j]; id[j] = ti;
                    }
                }
            }
            __syncthreads();
        }
    }
    for (int r = tid; r < NN; r += 1024) {
        float kv = kk[r];
        int pid = id[r];
        g_perm[r] = pid;
        g_irank[pid] = r;
        g_ers[r] = make_float2(expf(0.01f * kv), expf(kv));
    }
    for (int j = tid; j < NN; j += 1024) {
        float t = -g_scol[j];
        int lo = 0, hi = NN;
        while (lo < hi) {
            int mid = (lo + hi) >> 1;
            if (kk[mid] < t) lo = mid + 1; else hi = mid;
        }
        g_mj[j] = lo;
    }
}

// ---------------- K3: per-row scan (512 thr, 8 elem/thr) -> att + A planes ----------------
__global__ __launch_bounds__(512) void k_scan(const float* __restrict__ A) {
    __shared__ float ws[2 * (NN + 1) + 64];
    float* sPb = ws;
    float* sPc = ws + (NN + 1);
    float* wb  = ws + 2 * (NN + 1);
    float* wc  = wb + 16;

    int row = blockIdx.x;
    int tid = threadIdx.x;
    int lane = tid & 31;
    int wid = tid >> 5;           // 0..15
    int base = tid * 8;
    size_t orow = (size_t)row * NN;

    // load A row (2x float4), emit A hi/lo planes (uint4 stores)
    {
        float4 v0 = *(const float4*)(A + orow + base);
        float4 v1 = *(const float4*)(A + orow + base + 4);
        float f[8] = {v0.x, v0.y, v0.z, v0.w, v1.x, v1.y, v1.z, v1.w};
#pragma unroll
        for (int q = 0; q < 8; q++) ws[base + q] = f[q];
        uint16_t h[8], l[8];
#pragma unroll
        for (int q = 0; q < 8; q++) split_bf16(f[q], h[q], l[q]);
        uint4 hv, lv;
        hv.x = h[0] | (h[1] << 16); hv.y = h[2] | (h[3] << 16);
        hv.z = h[4] | (h[5] << 16); hv.w = h[6] | (h[7] << 16);
        lv.x = l[0] | (l[1] << 16); lv.y = l[2] | (l[3] << 16);
        lv.z = l[4] | (l[5] << 16); lv.w = l[6] | (l[7] << 16);
        *(uint4*)((uint16_t*)g_AH + orow + base) = hv;
        *(uint4*)((uint16_t*)g_AL + orow + base) = lv;
    }
    __syncthreads();

    float b[8], c[8];
    {
        int4 p0 = *(const int4*)(g_perm + base);
        int4 p1 = *(const int4*)(g_perm + base + 4);
        int pr[8] = {p0.x, p0.y, p0.z, p0.w, p1.x, p1.y, p1.z, p1.w};
#pragma unroll
        for (int q = 0; q < 8; q++) {
            float avv = ws[pr[q]];
            float2 e = g_ers[base + q];
            b[q] = avv * e.x;
            c[q] = avv * e.y;
        }
    }
    float lb = 0.f, lc = 0.f;
#pragma unroll
    for (int q = 0; q < 8; q++) { lb += b[q]; lc += c[q]; }

    float sb = lb, sc = lc;
#pragma unroll
    for (int off = 1; off < 32; off <<= 1) {
        float t1 = __shfl_up_sync(0xffffffffu, sb, off);
        float t2 = __shfl_up_sync(0xffffffffu, sc, off);
        if (lane >= off) { sb += t1; sc += t2; }
    }
    if (lane == 31) { wb[wid] = sb; wc[wid] = sc; }
    __syncthreads();
    if (wid == 0 && lane < 16) {
        float vb = wb[lane], vc = wc[lane];
#pragma unroll
        for (int off = 1; off < 16; off <<= 1) {
            float t1 = __shfl_up_sync(0x0000ffffu, vb, off);
            float t2 = __shfl_up_sync(0x0000ffffu, vc, off);
            if (lane >= off) { vb += t1; vc += t2; }
        }
        wb[lane] = vb; wc[lane] = vc;
    }
    __syncthreads();

    float offb = (wid ? wb[wid - 1] : 0.f) + (sb - lb);
    float offc = (wid ? wc[wid - 1] : 0.f) + (sc - lc);
    float rb = offb, rc = offc;
#pragma unroll
    for (int q = 0; q < 8; q++) {
        sPb[base + q] = rb; rb += b[q];
        sPc[base + q] = rc; rc += c[q];
    }
    if (tid == 511) { sPb[NN] = rb; sPc[NN] = rc; }
    __syncthreads();

    float Ctot = sPc[NN];
    int rank_i = g_irank[row];
    float er1u = g_er1u[row], er2u = g_er2u[row];
    {
        int4 m0v = *(const int4*)(g_mj + base);
        int4 m1v = *(const int4*)(g_mj + base + 4);
        int ms[8] = {m0v.x, m0v.y, m0v.z, m0v.w, m1v.x, m1v.y, m1v.z, m1v.w};
        uint16_t h[8], l[8];
#pragma unroll
        for (int q = 0; q < 8; q++) {
            int m = ms[q];
            float2 jc = g_ecs[base + q];
            float num = jc.x * sPb[m] + jc.y * (Ctot - sPc[m]);
            float den = (rank_i >= m) ? er2u * jc.y : er1u * jc.x;
            float att = (num != 0.f) ? __fdividef(den, num) : 0.f;
            split_bf16(att, h[q], l[q]);
        }
        uint4 hv, lv;
        hv.x = h[0] | (h[1] << 16); hv.y = h[2] | (h[3] << 16);
        hv.z = h[4] | (h[5] << 16); hv.w = h[6] | (h[7] << 16);
        lv.x = l[0] | (l[1] << 16); lv.y = l[2] | (l[3] << 16);
        lv.z = l[4] | (l[5] << 16); lv.w = l[6] | (l[7] << 16);
        *(uint4*)((uint16_t*)g_AttH + orow + base) = hv;
        *(uint4*)((uint16_t*)g_AttL + orow + base) = lv;
    }
}

// ---------------- K4: HMMA GEMM, 128x128 tile, 512 threads (16 warps, 32x32 each) ----------------
__global__ __launch_bounds__(512, 1) void mm_gemm(const __nv_bfloat16* __restrict__ Ah,
                                                  const __nv_bfloat16* __restrict__ Al,
                                                  const __nv_bfloat16* __restrict__ Bh,
                                                  const __nv_bfloat16* __restrict__ Bl,
                                                  float* __restrict__ Cpart) {
    extern __shared__ char smem[];
    uint32_t sb = smem_u32(smem);
    int tid = threadIdx.x;
    int lane = tid & 31;
    int wid = tid >> 5;       // 0..15
    int wm = wid >> 2;        // 0..3 (32-row slab)
    int wn = wid & 3;         // 0..3 (32-col slab)
    int m0 = blockIdx.x * 128;
    int s = blockIdx.y;
    int kbeg = s * (NN / SPLITK);

    auto issue = [&](int t) {
        int kt = kbeg + t * BK;
        uint32_t st = sb + (t & (STAGES - 1)) * STAGE_BYTES;
        {
            int rowa = tid >> 2, ca = tid & 3;     // 512 threads cover 128x4 chunks
            uint32_t dst = st + rowa * 64 + (((ca ^ ((rowa >> 1) & 3))) << 4);
            CP16(dst + AH_OFF, Ah + (size_t)(m0 + rowa) * NN + kt + ca * 8);
            CP16(dst + AL_OFF, Al + (size_t)(m0 + rowa) * NN + kt + ca * 8);
        }
        {
            int kb = tid >> 4, cb = tid & 15;      // 512 threads cover 32x16 chunks
            uint32_t dst = st + kb * 256 + (((cb ^ (kb & 7))) << 4);
            CP16(dst + BH_OFF, Bh + (size_t)(kt + kb) * FF + cb * 8);
            CP16(dst + BL_OFF, Bl + (size_t)(kt + kb) * FF + cb * 8);
        }
        CP_COMMIT();
    };

    issue(0); issue(1); issue(2);

    float acc[2][4][4];
#pragma unroll
    for (int i = 0; i < 2; i++)
#pragma unroll
        for (int j = 0; j < 4; j++)
#pragma unroll
            for (int r = 0; r < 4; r++) acc[i][j][r] = 0.f;

    for (int t = 0; t < KTILES; t++) {
        CP_WAIT2();
        __syncthreads();
        if (t + 3 < KTILES) issue(t + 3); else CP_COMMIT();

        uint32_t abase = sb + (t & (STAGES - 1)) * STAGE_BYTES;
#pragma unroll
        for (int ks = 0; ks < 2; ks++) {
            uint32_t ah[2][4], al[2][4], bhf[2][4], blf[2][4];
#pragma unroll
            for (int mt = 0; mt < 2; mt++) {
                int rowa = wm * 32 + mt * 16 + (lane & 7) + ((lane >> 3) & 1) * 8;
                int ca = 2 * ks + (lane >> 4);
                uint32_t addr = abase + rowa * 64 + (((ca ^ ((rowa >> 1) & 3))) << 4);
                ldsm4(ah[mt], addr + AH_OFF);
                ldsm4(al[mt], addr + AL_OFF);
            }
#pragma unroll
            for (int nh = 0; nh < 2; nh++) {
                int kb = ks * 16 + (lane & 7) + ((lane >> 3) & 1) * 8;
                int cb = wn * 4 + nh * 2 + (lane >> 4);
                uint32_t addr = abase + kb * 256 + (((cb ^ (kb & 7))) << 4);
                ldsm4t(bhf[nh], addr + BH_OFF);
                ldsm4t(blf[nh], addr + BL_OFF);
            }
#pragma unroll
            for (int mt = 0; mt < 2; mt++)
#pragma unroll
                for (int nt = 0; nt < 4; nt++)
                    mma16816(acc[mt][nt], ah[mt], &bhf[nt >> 1][(nt & 1) * 2]);
#pragma unroll
            for (int mt = 0; mt < 2; mt++)
#pragma unroll
                for (int nt = 0; nt < 4; nt++)
                    mma16816(acc[mt][nt], ah[mt], &blf[nt >> 1][(nt & 1) * 2]);
#pragma unroll
            for (int mt = 0; mt < 2; mt++)
#pragma unroll
                for (int nt = 0; nt < 4; nt++)
                    mma16816(acc[mt][nt], al[mt], &bhf[nt >> 1][(nt & 1) * 2]);
        }
    }

    float* C = Cpart + (size_t)s * (NN * FF);
#pragma unroll
    for (int mt = 0; mt < 2; mt++) {
#pragma unroll
        for (int nt = 0; nt < 4; nt++) {
            int rowc = m0 + wm * 32 + mt * 16 + (lane >> 2);
            int colc = wn * 32 + nt * 8 + (lane & 3) * 2;
            *(float2*)(C + (size_t)rowc * FF + colc) =
                make_float2(acc[mt][nt][0], acc[mt][nt][1]);
            *(float2*)(C + (size_t)(rowc + 8) * FF + colc) =
                make_float2(acc[mt][nt][2], acc[mt][nt][3]);
        }
    }
}

// ---------------- K5a: reduce partials -> fp32 out ----------------
__global__ void k_reduce(float* __restrict__ out) {
    int i = blockIdx.x * blockDim.x + threadIdx.x;
    if (i < NN * FF) {
        float s = 0.f;
#pragma unroll
        for (int p = 0; p < SPLITK; p++) s += g_part[(size_t)p * (NN * FF) + i];
        out[i] = s;
    }
}

// ---------------- K5b: reduce partials -> bf16 hi/lo B operand ----------------
__global__ void k_reduce_conv() {
    int i = blockIdx.x * blockDim.x + threadIdx.x;
    if (i < NN * FF) {
        float s = 0.f;
#pragma unroll
        for (int p = 0; p < SPLITK; p++) s += g_part[(size_t)p * (NN * FF) + i];
        uint16_t h, l;
        split_bf16(s, h, l);
        g_Bh[i] = *(__nv_bfloat16*)&h;
        g_Bl[i] = *(__nv_bfloat16*)&l;
    }
}

// ---------------- launcher ----------------
extern "C" void kernel_launch(void* const* d_in, const int* in_sizes, int n_in,
                              void* d_out, int out_size) {
    const float *X = nullptr, *A = nullptr, *W = nullptr, *av = nullptr;
    for (int i = 0; i < n_in; i++) {
        switch (in_sizes[i]) {
            case NN * FF: X = (const float*)d_in[i]; break;
            case NN * NN: A = (const float*)d_in[i]; break;
            case FF * FF: W = (const float*)d_in[i]; break;
            case 2 * FF:  av = (const float*)d_in[i]; break;
            default: break;
        }
    }
    float* H = (float*)d_out;

    __nv_bfloat16 *dAttH, *dAttL, *dAH, *dAL, *dBh, *dBl;
    float* dPart;
    cudaGetSymbolAddress((void**)&dAttH, g_AttH);
    cudaGetSymbolAddress((void**)&dAttL, g_AttL);
    cudaGetSymbolAddress((void**)&dAH, g_AH);
    cudaGetSymbolAddress((void**)&dAL, g_AL);
    cudaGetSymbolAddress((void**)&dBh, g_Bh);
    cudaGetSymbolAddress((void**)&dBl, g_Bl);
    cudaGetSymbolAddress((void**)&dPart, g_part);

    cudaFuncSetAttribute(mm_gemm, cudaFuncAttributeMaxDynamicSharedMemorySize,
                         STAGES * STAGE_BYTES);

    k_xw<<<NN / 16, 128>>>(X, W, av);
    k_sort<<<1, 1024>>>();
    k_scan<<<NN, 512>>>(A);

    dim3 grid(NN / 128, SPLITK);
    mm_gemm<<<grid, 512, STAGES * STAGE_BYTES>>>(dAttH, dAttL, dBh, dBl, dPart);
    k_reduce_conv<<<(NN * FF + 255) / 256, 256>>>();
    mm_gemm<<<grid, 512, STAGES * STAGE_BYTES>>>(dAH, dAL, dBh, dBl, dPart);
    k_reduce<<<(NN * FF + 255) / 256, 256>>>(H);
}

// round 8
// speedup vs baseline: 1.6009x; 1.6009x over previous
#include <cuda_runtime.h>
#include <cuda_fp16.h>
#include <cstdint>
#include <cstddef>

#define NN 4096
#define FF 128
#define SPLITK 8
#define BK 32
#define KTILES ((NN / SPLITK) / BK)   // 16
#define STAGES 4
#define STAGE_BYTES 24576
#define AF_OFF 0
#define BH_OFF 8192
#define BL_OFF 16384

// ---------------- scratch ----------------
__device__ float g_srow[NN];
__device__ float g_scol[NN];
__device__ float2 g_ecs[NN];   // (exp(0.01*scol), exp(scol))
__device__ float g_er1u[NN];
__device__ float g_er2u[NN];
__device__ float2 g_ers[NN];   // sorted-order (exp(0.01*s), exp(s))
__device__ int   g_perm[NN];
__device__ int   g_irank[NN];
__device__ int   g_mj[NN];
__device__ float g_part[(size_t)SPLITK * NN * FF];
__device__ __half g_Bh[NN * FF];            // B hi [k][n]
__device__ __half g_Bl[NN * FF];            // B lo
__device__ __half g_AttF[(size_t)NN * NN];  // att fp16 (GEMM1 A)
__device__ __half g_AF[(size_t)NN * NN];    // A fp16 (GEMM2 A)

// ---------------- helpers ----------------
__device__ __forceinline__ uint32_t smem_u32(const void* p) {
    uint32_t a;
    asm("{ .reg .u64 t; cvta.to.shared.u64 t, %1; cvt.u32.u64 %0, t; }" : "=r"(a) : "l"(p));
    return a;
}
__device__ __forceinline__ void ldsm4(uint32_t* r, uint32_t a) {
    asm volatile("ldmatrix.sync.aligned.m8n8.x4.shared.b16 {%0,%1,%2,%3}, [%4];"
        : "=r"(r[0]), "=r"(r[1]), "=r"(r[2]), "=r"(r[3]) : "r"(a));
}
__device__ __forceinline__ void ldsm4t(uint32_t* r, uint32_t a) {
    asm volatile("ldmatrix.sync.aligned.m8n8.x4.trans.shared.b16 {%0,%1,%2,%3}, [%4];"
        : "=r"(r[0]), "=r"(r[1]), "=r"(r[2]), "=r"(r[3]) : "r"(a));
}
__device__ __forceinline__ void mma16816(float* d, const uint32_t* a, const uint32_t* b) {
    asm volatile(
        "mma.sync.aligned.m16n8k16.row.col.f32.f16.f16.f32 "
        "{%0,%1,%2,%3}, {%4,%5,%6,%7}, {%8,%9}, {%0,%1,%2,%3};"
        : "+f"(d[0]), "+f"(d[1]), "+f"(d[2]), "+f"(d[3])
        : "r"(a[0]), "r"(a[1]), "r"(a[2]), "r"(a[3]), "r"(b[0]), "r"(b[1]));
}
__device__ __forceinline__ void split_f16(float f, uint16_t& h, uint16_t& l) {
    __half hb = __float2half_rn(f);
    float r = f - __half2float(hb);
    __half lb = __float2half_rn(r);
    h = *(uint16_t*)&hb;
    l = *(uint16_t*)&lb;
}
#define CP16(dst, src) \
    asm volatile("cp.async.cg.shared.global [%0], [%1], 16;" :: "r"(dst), "l"(src))
#define CP_COMMIT() asm volatile("cp.async.commit_group;" ::: "memory")
#define CP_WAIT2() asm volatile("cp.async.wait_group 2;" ::: "memory")

// ---------------- K1: XW = X @ W, emit fp16-split(XW) + sums + exp factors ----------------
__global__ __launch_bounds__(128) void k_xw(const float* __restrict__ X,
                                            const float* __restrict__ W,
                                            const float* __restrict__ av) {
    __shared__ float xr[16][FF];
    int j = threadIdx.x;
    int i0 = blockIdx.x * 16;
#pragma unroll
    for (int r = 0; r < 16; r++) xr[r][j] = X[(size_t)(i0 + r) * FF + j];
    __syncthreads();
    float acc[16];
#pragma unroll
    for (int r = 0; r < 16; r++) acc[r] = 0.f;
    for (int k = 0; k < FF; k++) {
        float w = W[k * FF + j];
#pragma unroll
        for (int r = 0; r < 16; r++) acc[r] += xr[r][k] * w;
    }
#pragma unroll
    for (int r = 0; r < 16; r++) {
        size_t idx = (size_t)(i0 + r) * FF + j;
        uint16_t h, l;
        split_f16(acc[r], h, l);
        g_Bh[idx] = *(__half*)&h;
        g_Bl[idx] = *(__half*)&l;
    }
    float ac = av[j], ar = av[FF + j];
    int lane = j & 31, w4 = j >> 5;
    __syncthreads();
#pragma unroll
    for (int r = 0; r < 16; r++) xr[r][j] = acc[r] * ac;
    __syncthreads();
#pragma unroll
    for (int rr = 0; rr < 4; rr++) {
        int r = w4 * 4 + rr;
        float v = xr[r][lane] + xr[r][lane + 32] + xr[r][lane + 64] + xr[r][lane + 96];
#pragma unroll
        for (int off = 16; off; off >>= 1) v += __shfl_down_sync(0xffffffffu, v, off);
        if (lane == 0) {
            g_scol[i0 + r] = v;
            g_ecs[i0 + r] = make_float2(expf(0.01f * v), expf(v));
        }
    }
    __syncthreads();
#pragma unroll
    for (int r = 0; r < 16; r++) xr[r][j] = acc[r] * ar;
    __syncthreads();
#pragma unroll
    for (int rr = 0; rr < 4; rr++) {
        int r = w4 * 4 + rr;
        float v = xr[r][lane] + xr[r][lane + 32] + xr[r][lane + 64] + xr[r][lane + 96];
#pragma unroll
        for (int off = 16; off; off >>= 1) v += __shfl_down_sync(0xffffffffu, v, off);
        if (lane == 0) {
            g_srow[i0 + r] = v;
            g_er1u[i0 + r] = expf(0.01f * v);
            g_er2u[i0 + r] = expf(v);
        }
    }
}

// ---------------- K2: rank-by-count (replaces bitonic sort) ----------------
// One warp per index i: rank_i = #{k: s_k<s_i or (s_k==s_i and k<i)},
// m_i = #{k: s_k < -scol_i}. Scatter perm/ers by rank.
__global__ __launch_bounds__(1024) void k_rank() {
    __shared__ float ss[NN];
    int tid = threadIdx.x;
    int lane = tid & 31;
    int wid = tid >> 5;               // 0..31
    int i = blockIdx.x * 32 + wid;    // grid 128 blocks
    for (int r = tid; r < NN; r += 1024) ss[r] = g_srow[r];
    __syncthreads();
    float si = ss[i];
    float tj = -g_scol[i];
    int rank = 0, m = 0;
    for (int k = lane; k < NN; k += 32) {
        float sk = ss[k];
        rank += (sk < si) || (sk == si && k < i);
        m += (sk < tj);
    }
#pragma unroll
    for (int off = 16; off; off >>= 1) {
        rank += __shfl_down_sync(0xffffffffu, rank, off);
        m    += __shfl_down_sync(0xffffffffu, m, off);
    }
    if (lane == 0) {
        g_irank[i] = rank;
        g_perm[rank] = i;
        g_mj[i] = m;
        g_ers[rank] = make_float2(g_er1u[i], g_er2u[i]);
    }
}

// ---------------- K3: per-row scan (1024 thr) -> att fp16 + A fp16 ----------------
__global__ __launch_bounds__(1024) void k_scan(const float* __restrict__ A) {
    __shared__ float ws[2 * (NN + 1) + 64];
    float* sPb = ws;
    float* sPc = ws + (NN + 1);
    float* wb  = ws + 2 * (NN + 1);
    float* wc  = wb + 32;

    int row = blockIdx.x;
    int tid = threadIdx.x;
    int lane = tid & 31;
    int wid = tid >> 5;
    int base = tid * 4;
    size_t orow = (size_t)row * NN;

    // load A row, emit fp16(A)
    {
        float4 va = *(const float4*)(A + orow + base);
        ws[base + 0] = va.x; ws[base + 1] = va.y;
        ws[base + 2] = va.z; ws[base + 3] = va.w;
        __half h0 = __float2half_rn(va.x), h1 = __float2half_rn(va.y);
        __half h2 = __float2half_rn(va.z), h3 = __float2half_rn(va.w);
        uint2 hv;
        hv.x = (uint32_t)*(uint16_t*)&h0 | ((uint32_t)*(uint16_t*)&h1 << 16);
        hv.y = (uint32_t)*(uint16_t*)&h2 | ((uint32_t)*(uint16_t*)&h3 << 16);
        *(uint2*)((uint16_t*)g_AF + orow + base) = hv;
    }
    __syncthreads();

    int4 pv = *(const int4*)(g_perm + base);
    int pr[4] = {pv.x, pv.y, pv.z, pv.w};
    float b[4], c[4];
#pragma unroll
    for (int q = 0; q < 4; q++) {
        float avv = ws[pr[q]];
        float2 e = g_ers[base + q];
        b[q] = avv * e.x;
        c[q] = avv * e.y;
    }
    float lb = b[0] + b[1] + b[2] + b[3];
    float lc = c[0] + c[1] + c[2] + c[3];

    float sb = lb, sc = lc;
#pragma unroll
    for (int off = 1; off < 32; off <<= 1) {
        float t1 = __shfl_up_sync(0xffffffffu, sb, off);
        float t2 = __shfl_up_sync(0xffffffffu, sc, off);
        if (lane >= off) { sb += t1; sc += t2; }
    }
    if (lane == 31) { wb[wid] = sb; wc[wid] = sc; }
    __syncthreads();
    if (wid == 0) {
        float vb = wb[lane], vc = wc[lane];
#pragma unroll
        for (int off = 1; off < 32; off <<= 1) {
            float t1 = __shfl_up_sync(0xffffffffu, vb, off);
            float t2 = __shfl_up_sync(0xffffffffu, vc, off);
            if (lane >= off) { vb += t1; vc += t2; }
        }
        wb[lane] = vb; wc[lane] = vc;
    }
    __syncthreads();

    float offb = (wid ? wb[wid - 1] : 0.f) + (sb - lb);
    float offc = (wid ? wc[wid - 1] : 0.f) + (sc - lc);
    float rb = offb, rc = offc;
#pragma unroll
    for (int q = 0; q < 4; q++) {
        sPb[base + q] = rb; rb += b[q];
        sPc[base + q] = rc; rc += c[q];
    }
    if (tid == 1023) { sPb[NN] = rb; sPc[NN] = rc; }
    __syncthreads();

    float Ctot = sPc[NN];
    int rank_i = g_irank[row];
    float er1u = g_er1u[row], er2u = g_er2u[row];
    {
        int4 mv = *(const int4*)(g_mj + base);
        int ms[4] = {mv.x, mv.y, mv.z, mv.w};
        uint16_t h[4];
#pragma unroll
        for (int q = 0; q < 4; q++) {
            int m = ms[q];
            float2 jc = g_ecs[base + q];
            float num = jc.x * sPb[m] + jc.y * (Ctot - sPc[m]);
            float den = (rank_i >= m) ? er2u * jc.y : er1u * jc.x;
            float att = (num != 0.f) ? __fdividef(den, num) : 0.f;
            __half ah = __float2half_rn(att);
            h[q] = *(uint16_t*)&ah;
        }
        uint2 hv;
        hv.x = h[0] | (h[1] << 16); hv.y = h[2] | (h[3] << 16);
        *(uint2*)((uint16_t*)g_AttF + orow + base) = hv;
    }
}

// ---------------- K4: HMMA GEMM, fp16 2-term, 128x128 tile, 256 threads ----------------
__global__ __launch_bounds__(256) void mm_gemm(const __half* __restrict__ Af,
                                               const __half* __restrict__ Bh,
                                               const __half* __restrict__ Bl,
                                               float* __restrict__ Cpart) {
    extern __shared__ char smem[];
    uint32_t sb = smem_u32(smem);
    int tid = threadIdx.x;
    int lane = tid & 31;
    int wid = tid >> 5;
    int wm = wid >> 2;        // 0..1
    int wn = wid & 3;         // 0..3
    int m0 = blockIdx.x * 128;
    int s = blockIdx.y;
    int kbeg = s * (NN / SPLITK);

    auto issue = [&](int t) {
        int kt = kbeg + t * BK;
        uint32_t st = sb + (t & (STAGES - 1)) * STAGE_BYTES;
#pragma unroll
        for (int q = 0; q < 2; q++) {
            int lin = tid + q * 256;
            int rowa = lin >> 2, ca = lin & 3;
            uint32_t dst = st + rowa * 64 + (((ca ^ ((rowa >> 1) & 3))) << 4);
            CP16(dst + AF_OFF, Af + (size_t)(m0 + rowa) * NN + kt + ca * 8);
        }
#pragma unroll
        for (int q = 0; q < 2; q++) {
            int lin = tid + q * 256;
            int kb = lin >> 4, cb = lin & 15;
            uint32_t dst = st + kb * 256 + (((cb ^ (kb & 7))) << 4);
            CP16(dst + BH_OFF, Bh + (size_t)(kt + kb) * FF + cb * 8);
            CP16(dst + BL_OFF, Bl + (size_t)(kt + kb) * FF + cb * 8);
        }
        CP_COMMIT();
    };

    issue(0); issue(1); issue(2);

    float acc[4][4][4];
#pragma unroll
    for (int i = 0; i < 4; i++)
#pragma unroll
        for (int j = 0; j < 4; j++)
#pragma unroll
            for (int r = 0; r < 4; r++) acc[i][j][r] = 0.f;

    for (int t = 0; t < KTILES; t++) {
        CP_WAIT2();
        __syncthreads();
        if (t + 3 < KTILES) issue(t + 3); else CP_COMMIT();

        uint32_t abase = sb + (t & (STAGES - 1)) * STAGE_BYTES;
#pragma unroll
        for (int ks = 0; ks < 2; ks++) {
            uint32_t af[4][4], bhf[2][4], blf[2][4];
#pragma unroll
            for (int mt = 0; mt < 4; mt++) {
                int rowa = wm * 64 + mt * 16 + (lane & 7) + ((lane >> 3) & 1) * 8;
                int ca = 2 * ks + (lane >> 4);
                uint32_t addr = abase + rowa * 64 + (((ca ^ ((rowa >> 1) & 3))) << 4);
                ldsm4(af[mt], addr + AF_OFF);
            }
#pragma unroll
            for (int nh = 0; nh < 2; nh++) {
                int kb = ks * 16 + (lane & 7) + ((lane >> 3) & 1) * 8;
                int cb = ((wn * 32 + nh * 16) >> 3) + (lane >> 4);
                uint32_t addr = abase + kb * 256 + (((cb ^ (kb & 7))) << 4);
                ldsm4t(bhf[nh], addr + BH_OFF);
                ldsm4t(blf[nh], addr + BL_OFF);
            }
#pragma unroll
            for (int mt = 0; mt < 4; mt++)
#pragma unroll
                for (int nt = 0; nt < 4; nt++)
                    mma16816(acc[mt][nt], af[mt], &bhf[nt >> 1][(nt & 1) * 2]);
#pragma unroll
            for (int mt = 0; mt < 4; mt++)
#pragma unroll
                for (int nt = 0; nt < 4; nt++)
                    mma16816(acc[mt][nt], af[mt], &blf[nt >> 1][(nt & 1) * 2]);
        }
    }

    float* C = Cpart + (size_t)s * (NN * FF);
#pragma unroll
    for (int mt = 0; mt < 4; mt++) {
#pragma unroll
        for (int nt = 0; nt < 4; nt++) {
            int rowc = m0 + wm * 64 + mt * 16 + (lane >> 2);
            int colc = wn * 32 + nt * 8 + (lane & 3) * 2;
            *(float2*)(C + (size_t)rowc * FF + colc) =
                make_float2(acc[mt][nt][0], acc[mt][nt][1]);
            *(float2*)(C + (size_t)(rowc + 8) * FF + colc) =
                make_float2(acc[mt][nt][2], acc[mt][nt][3]);
        }
    }
}

// ---------------- K5a: reduce partials -> fp32 out ----------------
__global__ void k_reduce(float* __restrict__ out) {
    int i = blockIdx.x * blockDim.x + threadIdx.x;
    if (i < NN * FF) {
        float s = 0.f;
#pragma unroll
        for (int p = 0; p < SPLITK; p++) s += g_part[(size_t)p * (NN * FF) + i];
        out[i] = s;
    }
}

// ---------------- K5b: reduce partials -> fp16-split B operand ----------------
__global__ void k_reduce_conv() {
    int i = blockIdx.x * blockDim.x + threadIdx.x;
    if (i < NN * FF) {
        float s = 0.f;
#pragma unroll
        for (int p = 0; p < SPLITK; p++) s += g_part[(size_t)p * (NN * FF) + i];
        uint16_t h, l;
        split_f16(s, h, l);
        g_Bh[i] = *(__half*)&h;
        g_Bl[i] = *(__half*)&l;
    }
}

// ---------------- launcher ----------------
extern "C" void kernel_launch(void* const* d_in, const int* in_sizes, int n_in,
                              void* d_out, int out_size) {
    const float *X = nullptr, *A = nullptr, *W = nullptr, *av = nullptr;
    for (int i = 0; i < n_in; i++) {
        switch (in_sizes[i]) {
            case NN * FF: X = (const float*)d_in[i]; break;
            case NN * NN: A = (const float*)d_in[i]; break;
            case FF * FF: W = (const float*)d_in[i]; break;
            case 2 * FF:  av = (const float*)d_in[i]; break;
            default: break;
        }
    }
    float* H = (float*)d_out;

    __half *dAttF, *dAF, *dBh, *dBl;
    float* dPart;
    cudaGetSymbolAddress((void**)&dAttF, g_AttF);
    cudaGetSymbolAddress((void**)&dAF, g_AF);
    cudaGetSymbolAddress((void**)&dBh, g_Bh);
    cudaGetSymbolAddress((void**)&dBl, g_Bl);
    cudaGetSymbolAddress((void**)&dPart, g_part);

    cudaFuncSetAttribute(mm_gemm, cudaFuncAttributeMaxDynamicSharedMemorySize,
                         STAGES * STAGE_BYTES);

    k_xw<<<NN / 16, 128>>>(X, W, av);
    k_rank<<<NN / 32, 1024>>>();
    k_scan<<<NN, 1024>>>(A);

    dim3 grid(NN / 128, SPLITK);
    mm_gemm<<<grid, 256, STAGES * STAGE_BYTES>>>(dAttF, dBh, dBl, dPart);
    k_reduce_conv<<<(NN * FF + 255) / 256, 256>>>();
    mm_gemm<<<grid, 256, STAGES * STAGE_BYTES>>>(dAF, dBh, dBl, dPart);
    k_reduce<<<(NN * FF + 255) / 256, 256>>>(H);
}

// round 9
// speedup vs baseline: 1.7562x; 1.0970x over previous
#include <cuda_runtime.h>
#include <cuda_fp16.h>
#include <cstdint>
#include <cstddef>

#define NN 4096
#define FF 128
#define SPLITK 8
#define BK 32
#define KTILES ((NN / SPLITK) / BK)   // 16
#define STAGES 4
#define STAGE_BYTES 16384
#define AF_OFF 0
#define BH_OFF 8192
#define SROWS 8

// ---------------- scratch ----------------
__device__ float g_srow[NN];
__device__ float g_scol[NN];
__device__ float2 g_ecs[NN];   // (exp(0.01*scol), exp(scol))
__device__ float g_er1u[NN];
__device__ float g_er2u[NN];
__device__ float2 g_ers[NN];   // sorted-order (exp(0.01*s), exp(s))
__device__ int   g_perm[NN];
__device__ int   g_irank[NN];
__device__ int   g_mj[NN];
__device__ float g_part[(size_t)SPLITK * NN * FF];
__device__ __half g_Bh[NN * FF];            // B fp16 [k][n]
__device__ __half g_AttF[(size_t)NN * NN];  // att fp16 (GEMM1 A)
__device__ __half g_AF[(size_t)NN * NN];    // A fp16 (GEMM2 A)

// ---------------- helpers ----------------
__device__ __forceinline__ uint32_t smem_u32(const void* p) {
    uint32_t a;
    asm("{ .reg .u64 t; cvta.to.shared.u64 t, %1; cvt.u32.u64 %0, t; }" : "=r"(a) : "l"(p));
    return a;
}
__device__ __forceinline__ void ldsm4(uint32_t* r, uint32_t a) {
    asm volatile("ldmatrix.sync.aligned.m8n8.x4.shared.b16 {%0,%1,%2,%3}, [%4];"
        : "=r"(r[0]), "=r"(r[1]), "=r"(r[2]), "=r"(r[3]) : "r"(a));
}
__device__ __forceinline__ void ldsm4t(uint32_t* r, uint32_t a) {
    asm volatile("ldmatrix.sync.aligned.m8n8.x4.trans.shared.b16 {%0,%1,%2,%3}, [%4];"
        : "=r"(r[0]), "=r"(r[1]), "=r"(r[2]), "=r"(r[3]) : "r"(a));
}
__device__ __forceinline__ void mma16816(float* d, const uint32_t* a, const uint32_t* b) {
    asm volatile(
        "mma.sync.aligned.m16n8k16.row.col.f32.f16.f16.f32 "
        "{%0,%1,%2,%3}, {%4,%5,%6,%7}, {%8,%9}, {%0,%1,%2,%3};"
        : "+f"(d[0]), "+f"(d[1]), "+f"(d[2]), "+f"(d[3])
        : "r"(a[0]), "r"(a[1]), "r"(a[2]), "r"(a[3]), "r"(b[0]), "r"(b[1]));
}
#define CP16(dst, src) \
    asm volatile("cp.async.cg.shared.global [%0], [%1], 16;" :: "r"(dst), "l"(src))
#define CP_COMMIT() asm volatile("cp.async.commit_group;" ::: "memory")
#define CP_WAIT2() asm volatile("cp.async.wait_group 2;" ::: "memory")
#define CP_WAIT0() asm volatile("cp.async.wait_group 0;" ::: "memory")

// ---------------- K1: XW = X @ W, emit fp16(XW) + sums + exp factors ----------------
__global__ __launch_bounds__(128) void k_xw(const float* __restrict__ X,
                                            const float* __restrict__ W,
                                            const float* __restrict__ av) {
    __shared__ float xr[16][FF];
    int j = threadIdx.x;
    int i0 = blockIdx.x * 16;
#pragma unroll
    for (int r = 0; r < 16; r++) xr[r][j] = X[(size_t)(i0 + r) * FF + j];
    __syncthreads();
    float acc[16];
#pragma unroll
    for (int r = 0; r < 16; r++) acc[r] = 0.f;
    for (int k = 0; k < FF; k++) {
        float w = W[k * FF + j];
#pragma unroll
        for (int r = 0; r < 16; r++) acc[r] += xr[r][k] * w;
    }
#pragma unroll
    for (int r = 0; r < 16; r++)
        g_Bh[(size_t)(i0 + r) * FF + j] = __float2half_rn(acc[r]);

    float ac = av[j], ar = av[FF + j];
    int lane = j & 31, w4 = j >> 5;
    __syncthreads();
#pragma unroll
    for (int r = 0; r < 16; r++) xr[r][j] = acc[r] * ac;
    __syncthreads();
#pragma unroll
    for (int rr = 0; rr < 4; rr++) {
        int r = w4 * 4 + rr;
        float v = xr[r][lane] + xr[r][lane + 32] + xr[r][lane + 64] + xr[r][lane + 96];
#pragma unroll
        for (int off = 16; off; off >>= 1) v += __shfl_down_sync(0xffffffffu, v, off);
        if (lane == 0) {
            g_scol[i0 + r] = v;
            g_ecs[i0 + r] = make_float2(expf(0.01f * v), expf(v));
        }
    }
    __syncthreads();
#pragma unroll
    for (int r = 0; r < 16; r++) xr[r][j] = acc[r] * ar;
    __syncthreads();
#pragma unroll
    for (int rr = 0; rr < 4; rr++) {
        int r = w4 * 4 + rr;
        float v = xr[r][lane] + xr[r][lane + 32] + xr[r][lane + 64] + xr[r][lane + 96];
#pragma unroll
        for (int off = 16; off; off >>= 1) v += __shfl_down_sync(0xffffffffu, v, off);
        if (lane == 0) {
            g_srow[i0 + r] = v;
            g_er1u[i0 + r] = expf(0.01f * v);
            g_er2u[i0 + r] = expf(v);
        }
    }
}

// ---------------- K2: rank-by-count ----------------
__global__ __launch_bounds__(1024) void k_rank() {
    __shared__ float ss[NN];
    int tid = threadIdx.x;
    int lane = tid & 31;
    int wid = tid >> 5;
    int i = blockIdx.x * 32 + wid;
    for (int r = tid; r < NN; r += 1024) ss[r] = g_srow[r];
    __syncthreads();
    float si = ss[i];
    float tj = -g_scol[i];
    int rank = 0, m = 0;
    for (int k = lane; k < NN; k += 32) {
        float sk = ss[k];
        rank += (sk < si) || (sk == si && k < i);
        m += (sk < tj);
    }
#pragma unroll
    for (int off = 16; off; off >>= 1) {
        rank += __shfl_down_sync(0xffffffffu, rank, off);
        m    += __shfl_down_sync(0xffffffffu, m, off);
    }
    if (lane == 0) {
        g_irank[i] = rank;
        g_perm[rank] = i;
        g_mj[i] = m;
        g_ers[rank] = make_float2(g_er1u[i], g_er2u[i]);
    }
}

// ---------------- K3: blockified scan, constants in smem + cp.async row prefetch ----------------
// grid NN/SROWS=512 blocks, 1024 threads, ~160KB dynamic smem.
#define SCAN_SMEM (32768 + 33056 + 16384 + 32768 + 32768 + 16384)
__global__ __launch_bounds__(1024) void k_scan(const float* __restrict__ A) {
    extern __shared__ char smem[];
    float* cA0 = (float*)smem;                         // [2][NN] = 32KB
    float* sP  = (float*)(smem + 32768);               // sPb(4097) sPc(4097) wb(32) wc(32)
    int*   cperm = (int*)(smem + 32768 + 33056);       // 16KB
    float2* cers = (float2*)(smem + 32768 + 33056 + 16384);   // 32KB
    float2* cecs = cers + NN;                          // 32KB
    int*   cmj  = (int*)(cecs + NN);                   // 16KB
    float* sPb = sP;
    float* sPc = sP + (NN + 1);
    float* wb  = sP + 2 * (NN + 1);
    float* wc  = wb + 32;

    int tid = threadIdx.x;
    int lane = tid & 31;
    int wid = tid >> 5;
    int base = tid * 4;
    int row0 = blockIdx.x * SROWS;

    // load broadcast constants once per block (coalesced)
    for (int r = tid; r < NN; r += 1024) {
        cperm[r] = g_perm[r];
        cers[r] = g_ers[r];
        cecs[r] = g_ecs[r];
        cmj[r] = g_mj[r];
    }

    // prefetch row 0
    {
        uint32_t dst = smem_u32(cA0) + tid * 16;
        CP16(dst, A + (size_t)row0 * NN + tid * 4);
        CP_COMMIT();
    }

    for (int rl = 0; rl < SROWS; rl++) {
        int row = row0 + rl;
        size_t orow = (size_t)row * NN;
        const float* arow = cA0 + (rl & 1) * NN;

        CP_WAIT0();
        __syncthreads();   // row rl present; constants present (first iter)

        // emit fp16(A) + gather in sorted order
        float4 va = *(const float4*)(arow + base);
        {
            __half h0 = __float2half_rn(va.x), h1 = __float2half_rn(va.y);
            __half h2 = __float2half_rn(va.z), h3 = __float2half_rn(va.w);
            uint2 hv;
            hv.x = (uint32_t)*(uint16_t*)&h0 | ((uint32_t)*(uint16_t*)&h1 << 16);
            hv.y = (uint32_t)*(uint16_t*)&h2 | ((uint32_t)*(uint16_t*)&h3 << 16);
            *(uint2*)((uint16_t*)g_AF + orow + base) = hv;
        }
        float b[4], c[4];
#pragma unroll
        for (int q = 0; q < 4; q++) {
            int r = base + q;
            float avv = arow[cperm[r]];
            float2 e = cers[r];
            b[q] = avv * e.x;
            c[q] = avv * e.y;
        }
        float lb = b[0] + b[1] + b[2] + b[3];
        float lc = c[0] + c[1] + c[2] + c[3];

        float sb = lb, sc = lc;
#pragma unroll
        for (int off = 1; off < 32; off <<= 1) {
            float t1 = __shfl_up_sync(0xffffffffu, sb, off);
            float t2 = __shfl_up_sync(0xffffffffu, sc, off);
            if (lane >= off) { sb += t1; sc += t2; }
        }
        if (lane == 31) { wb[wid] = sb; wc[wid] = sc; }
        __syncthreads();   // gathers complete

        // prefetch next row (overlaps with remaining scan work)
        if (rl + 1 < SROWS) {
            uint32_t dst = smem_u32(cA0) + ((rl + 1) & 1) * (NN * 4) + tid * 16;
            CP16(dst, A + (size_t)(row + 1) * NN + tid * 4);
            CP_COMMIT();
        }

        if (wid == 0) {
            float vb = wb[lane], vc = wc[lane];
#pragma unroll
            for (int off = 1; off < 32; off <<= 1) {
                float t1 = __shfl_up_sync(0xffffffffu, vb, off);
                float t2 = __shfl_up_sync(0xffffffffu, vc, off);
                if (lane >= off) { vb += t1; vc += t2; }
            }
            wb[lane] = vb; wc[lane] = vc;
        }
        __syncthreads();

        float offb = (wid ? wb[wid - 1] : 0.f) + (sb - lb);
        float offc = (wid ? wc[wid - 1] : 0.f) + (sc - lc);
        float rb = offb, rc = offc;
#pragma unroll
        for (int q = 0; q < 4; q++) {
            sPb[base + q] = rb; rb += b[q];
            sPc[base + q] = rc; rc += c[q];
        }
        if (tid == 1023) { sPb[NN] = rb; sPc[NN] = rc; }
        __syncthreads();

        float Ctot = sPc[NN];
        int rank_i = g_irank[row];
        float er1u = g_er1u[row], er2u = g_er2u[row];
        {
            uint16_t h[4];
#pragma unroll
            for (int q = 0; q < 4; q++) {
                int j = base + q;
                int m = cmj[j];
                float2 jc = cecs[j];
                float num = jc.x * sPb[m] + jc.y * (Ctot - sPc[m]);
                float den = (rank_i >= m) ? er2u * jc.y : er1u * jc.x;
                float att = (num != 0.f) ? __fdividef(den, num) : 0.f;
                __half ah = __float2half_rn(att);
                h[q] = *(uint16_t*)&ah;
            }
            uint2 hv;
            hv.x = h[0] | (h[1] << 16); hv.y = h[2] | (h[3] << 16);
            *(uint2*)((uint16_t*)g_AttF + orow + base) = hv;
        }
        __syncthreads();   // protect sP reuse next iteration
    }
}

// ---------------- K4: HMMA GEMM, single fp16 operands ----------------
__global__ __launch_bounds__(256) void mm_gemm(const __half* __restrict__ Af,
                                               const __half* __restrict__ Bh,
                                               float* __restrict__ Cpart) {
    extern __shared__ char smem[];
    uint32_t sb = smem_u32(smem);
    int tid = threadIdx.x;
    int lane = tid & 31;
    int wid = tid >> 5;
    int wm = wid >> 2;
    int wn = wid & 3;
    int m0 = blockIdx.x * 128;
    int s = blockIdx.y;
    int kbeg = s * (NN / SPLITK);

    auto issue = [&](int t) {
        int kt = kbeg + t * BK;
        uint32_t st = sb + (t & (STAGES - 1)) * STAGE_BYTES;
#pragma unroll
        for (int q = 0; q < 2; q++) {
            int lin = tid + q * 256;
            int rowa = lin >> 2, ca = lin & 3;
            uint32_t dst = st + rowa * 64 + (((ca ^ ((rowa >> 1) & 3))) << 4);
            CP16(dst + AF_OFF, Af + (size_t)(m0 + rowa) * NN + kt + ca * 8);
        }
#pragma unroll
        for (int q = 0; q < 2; q++) {
            int lin = tid + q * 256;
            int kb = lin >> 4, cb = lin & 15;
            uint32_t dst = st + kb * 256 + (((cb ^ (kb & 7))) << 4);
            CP16(dst + BH_OFF, Bh + (size_t)(kt + kb) * FF + cb * 8);
        }
        CP_COMMIT();
    };

    issue(0); issue(1); issue(2);

    float acc[4][4][4];
#pragma unroll
    for (int i = 0; i < 4; i++)
#pragma unroll
        for (int j = 0; j < 4; j++)
#pragma unroll
            for (int r = 0; r < 4; r++) acc[i][j][r] = 0.f;

    for (int t = 0; t < KTILES; t++) {
        CP_WAIT2();
        __syncthreads();
        if (t + 3 < KTILES) issue(t + 3); else CP_COMMIT();

        uint32_t abase = sb + (t & (STAGES - 1)) * STAGE_BYTES;
#pragma unroll
        for (int ks = 0; ks < 2; ks++) {
            uint32_t af[4][4], bhf[2][4];
#pragma unroll
            for (int mt = 0; mt < 4; mt++) {
                int rowa = wm * 64 + mt * 16 + (lane & 7) + ((lane >> 3) & 1) * 8;
                int ca = 2 * ks + (lane >> 4);
                uint32_t addr = abase + rowa * 64 + (((ca ^ ((rowa >> 1) & 3))) << 4);
                ldsm4(af[mt], addr + AF_OFF);
            }
#pragma unroll
            for (int nh = 0; nh < 2; nh++) {
                int kb = ks * 16 + (lane & 7) + ((lane >> 3) & 1) * 8;
                int cb = ((wn * 32 + nh * 16) >> 3) + (lane >> 4);
                uint32_t addr = abase + kb * 256 + (((cb ^ (kb & 7))) << 4);
                ldsm4t(bhf[nh], addr + BH_OFF);
            }
#pragma unroll
            for (int mt = 0; mt < 4; mt++)
#pragma unroll
                for (int nt = 0; nt < 4; nt++)
                    mma16816(acc[mt][nt], af[mt], &bhf[nt >> 1][(nt & 1) * 2]);
        }
    }

    float* C = Cpart + (size_t)s * (NN * FF);
#pragma unroll
    for (int mt = 0; mt < 4; mt++) {
#pragma unroll
        for (int nt = 0; nt < 4; nt++) {
            int rowc = m0 + wm * 64 + mt * 16 + (lane >> 2);
            int colc = wn * 32 + nt * 8 + (lane & 3) * 2;
            *(float2*)(C + (size_t)rowc * FF + colc) =
                make_float2(acc[mt][nt][0], acc[mt][nt][1]);
            *(float2*)(C + (size_t)(rowc + 8) * FF + colc) =
                make_float2(acc[mt][nt][2], acc[mt][nt][3]);
        }
    }
}

// ---------------- K5a: reduce partials -> fp32 out ----------------
__global__ void k_reduce(float* __restrict__ out) {
    int i = blockIdx.x * blockDim.x + threadIdx.x;
    if (i < NN * FF) {
        float s = 0.f;
#pragma unroll
        for (int p = 0; p < SPLITK; p++) s += g_part[(size_t)p * (NN * FF) + i];
        out[i] = s;
    }
}

// ---------------- K5b: reduce partials -> fp16 B operand ----------------
__global__ void k_reduce_conv() {
    int i = blockIdx.x * blockDim.x + threadIdx.x;
    if (i < NN * FF) {
        float s = 0.f;
#pragma unroll
        for (int p = 0; p < SPLITK; p++) s += g_part[(size_t)p * (NN * FF) + i];
        g_Bh[i] = __float2half_rn(s);
    }
}

// ---------------- launcher ----------------
extern "C" void kernel_launch(void* const* d_in, const int* in_sizes, int n_in,
                              void* d_out, int out_size) {
    const float *X = nullptr, *A = nullptr, *W = nullptr, *av = nullptr;
    for (int i = 0; i < n_in; i++) {
        switch (in_sizes[i]) {
            case NN * FF: X = (const float*)d_in[i]; break;
            case NN * NN: A = (const float*)d_in[i]; break;
            case FF * FF: W = (const float*)d_in[i]; break;
            case 2 * FF:  av = (const float*)d_in[i]; break;
            default: break;
        }
    }
    float* H = (float*)d_out;

    __half *dAttF, *dAF, *dBh;
    float* dPart;
    cudaGetSymbolAddress((void**)&dAttF, g_AttF);
    cudaGetSymbolAddress((void**)&dAF, g_AF);
    cudaGetSymbolAddress((void**)&dBh, g_Bh);
    cudaGetSymbolAddress((void**)&dPart, g_part);

    cudaFuncSetAttribute(mm_gemm, cudaFuncAttributeMaxDynamicSharedMemorySize,
                         STAGES * STAGE_BYTES);
    cudaFuncSetAttribute(k_scan, cudaFuncAttributeMaxDynamicSharedMemorySize,
                         SCAN_SMEM);

    k_xw<<<NN / 16, 128>>>(X, W, av);
    k_rank<<<NN / 32, 1024>>>();
    k_scan<<<NN / SROWS, 1024, SCAN_SMEM>>>(A);

    dim3 grid(NN / 128, SPLITK);
    mm_gemm<<<grid, 256, STAGES * STAGE_BYTES>>>(dAttF, dBh, dPart);
    k_reduce_conv<<<(NN * FF + 255) / 256, 256>>>();
    mm_gemm<<<grid, 256, STAGES * STAGE_BYTES>>>(dAF, dBh, dPart);
    k_reduce<<<(NN * FF + 255) / 256, 256>>>(H);
}